// round 1
// baseline (speedup 1.0000x reference)
#include <cuda_runtime.h>
#include <cstdint>

#define N_NODES 50000
#define N_EDGES 800000
#define D 64

// Scratch accumulator for scatter-sum (device global: no allocations allowed).
__device__ float g_acc[N_NODES * D];

// ---------------------------------------------------------------------------
// Kernel 1: zero the accumulator (vectorized).
// ---------------------------------------------------------------------------
__global__ void zero_acc_kernel() {
    int idx = blockIdx.x * blockDim.x + threadIdx.x;
    int total = (N_NODES * D) / 4;
    if (idx < total) {
        ((float4*)g_acc)[idx] = make_float4(0.f, 0.f, 0.f, 0.f);
    }
}

// ---------------------------------------------------------------------------
// Kernel 2: edge gather + scatter.
//   msg = embed[src] * out_deg[src] * w ; acc[dst] += msg
// 16 threads per edge, each handles one float4 chunk of D=64.
// Vector reduction red.global.add.v4.f32 (sm_90+): 1 op per 16B.
// ---------------------------------------------------------------------------
__global__ void edge_kernel(const float* __restrict__ embed,
                            const int* __restrict__ src,
                            const int* __restrict__ dst,
                            const float* __restrict__ ew,
                            const float* __restrict__ outdeg) {
    int gid = blockIdx.x * blockDim.x + threadIdx.x;
    int e = gid >> 4;
    if (e >= N_EDGES) return;
    int c = gid & 15;

    int s = src[e];
    int d = dst[e];
    float w = ew[e] * outdeg[s];

    const float4* ep = (const float4*)(embed + (size_t)s * D) + c;
    float4 v = __ldg(ep);
    v.x *= w; v.y *= w; v.z *= w; v.w *= w;

    float* ap = g_acc + (size_t)d * D + c * 4;
    asm volatile("red.global.add.v4.f32 [%0], {%1, %2, %3, %4};"
                 :: "l"(ap), "f"(v.x), "f"(v.y), "f"(v.z), "f"(v.w)
                 : "memory");
}

// ---------------------------------------------------------------------------
// Kernel 3: out = LeakyReLU((embed + acc*in_deg) @ W^T + b)
// One warp per row. x row in 2 regs/lane, broadcast via shfl.
// W stored transposed in smem: Wt[k][j] = W[j][k]; lane j reads float2 at
// Wt[k*64 + 2*j] -> conflict-free 64-bit LDS, two output cols per lane.
// ---------------------------------------------------------------------------
__global__ void out_kernel(const float* __restrict__ embed,
                           const float* __restrict__ indeg,
                           const float* __restrict__ W,
                           const float* __restrict__ b,
                           float* __restrict__ out) {
    __shared__ float Wt[D * D];
    __shared__ float bs[D];

    for (int i = threadIdx.x; i < D * D; i += blockDim.x) {
        int j = i >> 6;       // output col
        int k = i & 63;       // input dim
        Wt[k * D + j] = W[i]; // W row-major [j][k] -> Wt[k][j]
    }
    if (threadIdx.x < D) bs[threadIdx.x] = b[threadIdx.x];
    __syncthreads();

    int warp = threadIdx.x >> 5;
    int lane = threadIdx.x & 31;
    int warps_per_block = blockDim.x >> 5;
    int nwarps = warps_per_block * gridDim.x;

    for (int r = blockIdx.x * warps_per_block + warp; r < N_NODES; r += nwarps) {
        float ind = indeg[r];
        const float* eb = embed + (size_t)r * D;
        const float* ac = g_acc + (size_t)r * D;

        float x0 = eb[lane]      + ac[lane]      * ind;
        float x1 = eb[lane + 32] + ac[lane + 32] * ind;

        float2 acc = make_float2(bs[2 * lane], bs[2 * lane + 1]);

#pragma unroll
        for (int k = 0; k < D; k++) {
            float xk = __shfl_sync(0xffffffffu, (k < 32) ? x0 : x1, k & 31);
            float2 wv = *(const float2*)(Wt + k * D + 2 * lane);
            acc.x = fmaf(xk, wv.x, acc.x);
            acc.y = fmaf(xk, wv.y, acc.y);
        }

        acc.x = acc.x > 0.f ? acc.x : 0.01f * acc.x;
        acc.y = acc.y > 0.f ? acc.y : 0.01f * acc.y;
        *(float2*)(out + (size_t)r * D + 2 * lane) = acc;
    }
}

// ---------------------------------------------------------------------------
// kernel_launch
// inputs: 0 entity_embed [N*D] f32, 1 src [E] i32, 2 dst [E] i32,
//         3 edge_weight [E] f32, 4 out_sqrt_degree [N] f32,
//         5 in_sqrt_degree [N] f32, 6 W [D*D] f32, 7 b [D] f32
// ---------------------------------------------------------------------------
extern "C" void kernel_launch(void* const* d_in, const int* in_sizes, int n_in,
                              void* d_out, int out_size) {
    const float* embed  = (const float*)d_in[0];
    const int*   src    = (const int*)d_in[1];
    const int*   dst    = (const int*)d_in[2];
    const float* ew     = (const float*)d_in[3];
    const float* outdeg = (const float*)d_in[4];
    const float* indeg  = (const float*)d_in[5];
    const float* W      = (const float*)d_in[6];
    const float* b      = (const float*)d_in[7];
    float* out = (float*)d_out;

    // zero accumulator
    {
        int total = (N_NODES * D) / 4;
        int threads = 256;
        int blocks = (total + threads - 1) / threads;
        zero_acc_kernel<<<blocks, threads>>>();
    }

    // edge gather/scatter
    {
        long long total = (long long)N_EDGES * 16;
        int threads = 256;
        int blocks = (int)((total + threads - 1) / threads);
        edge_kernel<<<blocks, threads>>>(embed, src, dst, ew, outdeg);
    }

    // fused degree-scale + GEMM + LeakyReLU
    {
        int threads = 256;          // 8 warps -> 8 rows per block iteration
        int blocks = 148 * 8;       // grid-stride over rows, W loaded once/block
        out_kernel<<<blocks, threads>>>(embed, indeg, W, b, out);
    }
}